// round 1
// baseline (speedup 1.0000x reference)
#include <cuda_runtime.h>

// Problem constants (from reference)
#define B        4096
#define N_ELEM   2048
#define N_NODES  1024
#define E2       4096
#define THREADS  256

// Cross-block accumulator (double for safe summation across 4096 blocks).
__device__ double g_acc;

__global__ void nel_zero_kernel() {
    g_acc = 0.0;
}

__global__ __launch_bounds__(THREADS)
void nel_main_kernel(const float* __restrict__ EA,
                     const float* __restrict__ e,
                     const float* __restrict__ q,
                     const float* __restrict__ r,
                     const float* __restrict__ vecs,
                     const int*   __restrict__ node_ids,
                     const int*   __restrict__ elem_ids) {
    __shared__ float s_axial[N_ELEM];        // 8 KB
    __shared__ float s_res[N_NODES * 2];     // 8 KB
    __shared__ float s_part[THREADS / 32];

    const int b   = blockIdx.x;
    const int tid = threadIdx.x;

    // --- Stage axial = EA * e (coalesced float4) and zero residual ---
    const float4* EA4 = (const float4*)(EA + (size_t)b * N_ELEM);
    const float4* e4  = (const float4*)(e  + (size_t)b * N_ELEM);
    float4* sax4 = (float4*)s_axial;
    float4* sre4 = (float4*)s_res;

    #pragma unroll
    for (int i = tid; i < N_ELEM / 4; i += THREADS) {
        float4 a  = EA4[i];
        float4 ee = e4[i];
        sax4[i] = make_float4(a.x * ee.x, a.y * ee.y, a.z * ee.z, a.w * ee.w);
    }
    #pragma unroll
    for (int i = tid; i < (N_NODES * 2) / 4; i += THREADS) {
        sre4[i] = make_float4(0.f, 0.f, 0.f, 0.f);
    }
    __syncthreads();

    // --- Scatter: 4096 edges, 16 per thread, shared atomics ---
    #pragma unroll
    for (int k = 0; k < E2 / THREADS; k++) {
        int i   = tid + k * THREADS;
        int eid = __ldg(&elem_ids[i]);
        int nid = __ldg(&node_ids[i]);
        float2 v = __ldg((const float2*)(vecs + 2 * (size_t)i));
        float ax = s_axial[eid];
        atomicAdd(&s_res[nid * 2 + 0], ax * v.x);
        atomicAdd(&s_res[nid * 2 + 1], ax * v.y);
    }
    __syncthreads();

    // --- Residual - q - r, square, accumulate (coalesced float4) ---
    const float4* q4 = (const float4*)(q + (size_t)b * N_NODES * 2);
    const float4* r4 = (const float4*)(r + (size_t)b * N_NODES * 2);
    float acc = 0.f;
    #pragma unroll
    for (int i = tid; i < (N_NODES * 2) / 4; i += THREADS) {
        float4 qq = q4[i];
        float4 rr = r4[i];
        float4 ss = sre4[i];
        float dx = ss.x - qq.x - rr.x;
        float dy = ss.y - qq.y - rr.y;
        float dz = ss.z - qq.z - rr.z;
        float dw = ss.w - qq.w - rr.w;
        acc += dx * dx + dy * dy + dz * dz + dw * dw;
    }

    // --- Block reduction ---
    #pragma unroll
    for (int o = 16; o > 0; o >>= 1)
        acc += __shfl_down_sync(0xffffffffu, acc, o);
    if ((tid & 31) == 0) s_part[tid >> 5] = acc;
    __syncthreads();
    if (tid == 0) {
        float total = 0.f;
        #pragma unroll
        for (int w = 0; w < THREADS / 32; w++) total += s_part[w];
        atomicAdd(&g_acc, (double)total);
    }
}

__global__ void nel_finalize_kernel(float* __restrict__ out) {
    const double cnt = (double)B * (double)N_NODES * 2.0;
    *out = (float)(g_acc / cnt);
}

extern "C" void kernel_launch(void* const* d_in, const int* in_sizes, int n_in,
                              void* d_out, int out_size) {
    const float* EA       = (const float*)d_in[0];
    const float* e        = (const float*)d_in[1];
    const float* q        = (const float*)d_in[2];
    const float* r        = (const float*)d_in[3];
    const float* vecs     = (const float*)d_in[4];
    const int*   node_ids = (const int*)d_in[5];
    const int*   elem_ids = (const int*)d_in[6];
    float* out = (float*)d_out;

    nel_zero_kernel<<<1, 1>>>();
    nel_main_kernel<<<B, THREADS>>>(EA, e, q, r, vecs, node_ids, elem_ids);
    nel_finalize_kernel<<<1, 1>>>(out);
}

// round 2
// speedup vs baseline: 1.5846x; 1.5846x over previous
#include <cuda_runtime.h>

// Problem constants (from reference)
#define B        4096
#define N_ELEM   2048
#define N_NODES  1024
#define E2       4096
#define G        2                 // batches per block
#define NBLK     (B / G)           // 2048 blocks
#define THREADS  256

// Scratch in __device__ globals (no allocation allowed).
__device__ int    g_csr_off[N_NODES + 1];
__device__ int    g_csr_elem[E2];
__device__ float2 g_csr_vec[E2];
__device__ float  g_part[NBLK];
__device__ int    g_ctr = 0;

// ---------------------------------------------------------------------------
// Setup: build a deterministic CSR (edges grouped by node, sorted by original
// edge index within each node) from node_ids/elem_ids/vecs. One block.
// ---------------------------------------------------------------------------
__global__ __launch_bounds__(N_NODES)
void nel_setup_kernel(const int* __restrict__ node_ids,
                      const int* __restrict__ elem_ids,
                      const float* __restrict__ vecs) {
    __shared__ int s_beg[N_NODES];   // histogram, then exclusive offsets
    __shared__ int s_cur[N_NODES];   // scan buffer, then mutable cursor (=end)
    __shared__ int s_idx[E2];        // permutation (original edge index)
    const int tid = threadIdx.x;

    // 1. histogram
    s_beg[tid] = 0;
    __syncthreads();
    #pragma unroll
    for (int i = tid; i < E2; i += N_NODES)
        atomicAdd(&s_beg[node_ids[i]], 1);
    __syncthreads();

    // 2. exclusive scan (Hillis-Steele on 1024 elems)
    const int cnt = s_beg[tid];
    s_cur[tid] = cnt;
    __syncthreads();
    for (int s = 1; s < N_NODES; s <<= 1) {
        int v = (tid >= s) ? s_cur[tid - s] : 0;
        __syncthreads();
        s_cur[tid] += v;
        __syncthreads();
    }
    const int excl = s_cur[tid] - cnt;
    __syncthreads();
    s_beg[tid] = excl;
    s_cur[tid] = excl;
    __syncthreads();

    // 3. scatter edge indices into bins (order nondeterministic here)
    #pragma unroll
    for (int i = tid; i < E2; i += N_NODES) {
        int pos = atomicAdd(&s_cur[node_ids[i]], 1);
        s_idx[pos] = i;
    }
    __syncthreads();

    // 4. per-bin insertion sort by original index -> fully deterministic CSR
    {
        const int beg = s_beg[tid], end = s_cur[tid];
        for (int a = beg + 1; a < end; a++) {
            int key = s_idx[a];
            int p = a - 1;
            while (p >= beg && s_idx[p] > key) { s_idx[p + 1] = s_idx[p]; p--; }
            s_idx[p + 1] = key;
        }
    }
    __syncthreads();

    // 5. write out CSR
    g_csr_off[tid] = s_beg[tid];
    if (tid == 0) g_csr_off[N_NODES] = E2;
    #pragma unroll
    for (int i = tid; i < E2; i += N_NODES) {
        int idx = s_idx[i];
        g_csr_elem[i] = elem_ids[idx];
        g_csr_vec[i]  = make_float2(vecs[2 * idx], vecs[2 * idx + 1]);
    }
}

// ---------------------------------------------------------------------------
// Main: one block handles G batch rows. Stage axial in smem, gather via CSR
// (no atomics), fuse residual + squared-error reduction, last block finalizes.
// ---------------------------------------------------------------------------
__global__ __launch_bounds__(THREADS)
void nel_main_kernel(const float* __restrict__ EA,
                     const float* __restrict__ e,
                     const float* __restrict__ q,
                     const float* __restrict__ r,
                     float* __restrict__ out) {
    __shared__ float  s_axial[G * N_ELEM];   // 16 KB
    __shared__ float  s_warp[THREADS / 32];
    __shared__ int    s_islast;

    const int tid = threadIdx.x;
    const int b0  = blockIdx.x * G;

    // --- axial = EA * e for G contiguous batch rows (coalesced float4) ---
    const float4* EA4 = (const float4*)(EA + (size_t)b0 * N_ELEM);
    const float4* e4  = (const float4*)(e  + (size_t)b0 * N_ELEM);
    float4* sax4 = (float4*)s_axial;
    #pragma unroll
    for (int i = tid; i < (G * N_ELEM) / 4; i += THREADS) {
        float4 a  = EA4[i];
        float4 ee = e4[i];
        sax4[i] = make_float4(a.x * ee.x, a.y * ee.y, a.z * ee.z, a.w * ee.w);
    }
    __syncthreads();

    // --- gather per node, subtract q+r, square, accumulate ---
    const float2* q2 = (const float2*)(q + (size_t)b0 * N_NODES * 2);
    const float2* r2 = (const float2*)(r + (size_t)b0 * N_NODES * 2);
    float acc = 0.f;

    #pragma unroll
    for (int nn = 0; nn < N_NODES / THREADS; nn++) {
        const int n   = tid + nn * THREADS;
        const int beg = g_csr_off[n];
        const int end = g_csr_off[n + 1];

        float rx0 = 0.f, ry0 = 0.f, rx1 = 0.f, ry1 = 0.f;
        for (int p = beg; p < end; p++) {
            int    eid = g_csr_elem[p];
            float2 v   = g_csr_vec[p];
            float  a0  = s_axial[eid];
            float  a1  = s_axial[N_ELEM + eid];
            rx0 += a0 * v.x;  ry0 += a0 * v.y;
            rx1 += a1 * v.x;  ry1 += a1 * v.y;
        }
        float2 qq0 = q2[n];             float2 rr0 = r2[n];
        float2 qq1 = q2[N_NODES + n];   float2 rr1 = r2[N_NODES + n];
        float dx0 = rx0 - qq0.x - rr0.x, dy0 = ry0 - qq0.y - rr0.y;
        float dx1 = rx1 - qq1.x - rr1.x, dy1 = ry1 - qq1.y - rr1.y;
        acc += dx0 * dx0 + dy0 * dy0 + dx1 * dx1 + dy1 * dy1;
    }

    // --- block reduce ---
    #pragma unroll
    for (int o = 16; o > 0; o >>= 1)
        acc += __shfl_down_sync(0xffffffffu, acc, o);
    if ((tid & 31) == 0) s_warp[tid >> 5] = acc;
    __syncthreads();
    if (tid == 0) {
        float total = 0.f;
        #pragma unroll
        for (int w = 0; w < THREADS / 32; w++) total += s_warp[w];
        g_part[blockIdx.x] = total;
    }

    // --- last-block finalize (fixed-order double sum -> deterministic) ---
    __threadfence();
    if (tid == 0) {
        int old = atomicAdd(&g_ctr, 1);
        s_islast = (old == (int)gridDim.x - 1) ? 1 : 0;
    }
    __syncthreads();
    if (s_islast) {
        __threadfence();
        __shared__ double s_d[THREADS];
        double d = 0.0;
        #pragma unroll
        for (int i = tid; i < NBLK; i += THREADS) d += (double)g_part[i];
        s_d[tid] = d;
        __syncthreads();
        #pragma unroll
        for (int s = THREADS / 2; s > 0; s >>= 1) {
            if (tid < s) s_d[tid] += s_d[tid + s];
            __syncthreads();
        }
        if (tid == 0) {
            out[0] = (float)(s_d[0] / ((double)B * (double)N_NODES * 2.0));
            g_ctr = 0;   // reset for next graph replay
        }
    }
}

extern "C" void kernel_launch(void* const* d_in, const int* in_sizes, int n_in,
                              void* d_out, int out_size) {
    const float* EA       = (const float*)d_in[0];
    const float* e        = (const float*)d_in[1];
    const float* q        = (const float*)d_in[2];
    const float* r        = (const float*)d_in[3];
    const float* vecs     = (const float*)d_in[4];
    const int*   node_ids = (const int*)d_in[5];
    const int*   elem_ids = (const int*)d_in[6];
    float* out = (float*)d_out;

    nel_setup_kernel<<<1, N_NODES>>>(node_ids, elem_ids, vecs);
    nel_main_kernel<<<NBLK, THREADS>>>(EA, e, q, r, out);
}

// round 3
// speedup vs baseline: 1.6175x; 1.0208x over previous
#include <cuda_runtime.h>

// Problem constants (from reference)
#define B        4096
#define N_ELEM   2048
#define N_NODES  1024
#define E2       4096
#define G        4                 // batches per block
#define NBLK     (B / G)           // 1024 blocks
#define THREADS  256

// Scratch in __device__ globals (no allocation allowed).
__device__ int    g_csr_off[N_NODES + 1];
__device__ float4 g_csr[E2];       // {elem_as_float_bits, vx, vy, 0}
__device__ float  g_part[NBLK];
__device__ int    g_ctr = 0;

// ---------------------------------------------------------------------------
// Setup: deterministic CSR (edges grouped by node, sorted by original edge
// index within each node). One block, 1024 threads.
// ---------------------------------------------------------------------------
__global__ __launch_bounds__(N_NODES)
void nel_setup_kernel(const int* __restrict__ node_ids,
                      const int* __restrict__ elem_ids,
                      const float* __restrict__ vecs) {
    __shared__ int s_beg[N_NODES];
    __shared__ int s_cur[N_NODES];
    __shared__ int s_idx[E2];
    const int tid = threadIdx.x;

    // 1. histogram
    s_beg[tid] = 0;
    __syncthreads();
    #pragma unroll
    for (int i = tid; i < E2; i += N_NODES)
        atomicAdd(&s_beg[node_ids[i]], 1);
    __syncthreads();

    // 2. exclusive scan (Hillis-Steele)
    const int cnt = s_beg[tid];
    s_cur[tid] = cnt;
    __syncthreads();
    for (int s = 1; s < N_NODES; s <<= 1) {
        int v = (tid >= s) ? s_cur[tid - s] : 0;
        __syncthreads();
        s_cur[tid] += v;
        __syncthreads();
    }
    const int excl = s_cur[tid] - cnt;
    __syncthreads();
    s_beg[tid] = excl;
    s_cur[tid] = excl;
    __syncthreads();

    // 3. scatter edge indices into bins
    #pragma unroll
    for (int i = tid; i < E2; i += N_NODES) {
        int pos = atomicAdd(&s_cur[node_ids[i]], 1);
        s_idx[pos] = i;
    }
    __syncthreads();

    // 4. per-bin insertion sort -> deterministic order
    {
        const int beg = s_beg[tid], end = s_cur[tid];
        for (int a = beg + 1; a < end; a++) {
            int key = s_idx[a];
            int p = a - 1;
            while (p >= beg && s_idx[p] > key) { s_idx[p + 1] = s_idx[p]; p--; }
            s_idx[p + 1] = key;
        }
    }
    __syncthreads();

    // 5. write CSR (fused 16B records)
    g_csr_off[tid] = s_beg[tid];
    if (tid == 0) g_csr_off[N_NODES] = E2;
    #pragma unroll
    for (int i = tid; i < E2; i += N_NODES) {
        int idx = s_idx[i];
        float4 rec;
        rec.x = __int_as_float(elem_ids[idx]);
        rec.y = vecs[2 * idx];
        rec.z = vecs[2 * idx + 1];
        rec.w = 0.f;
        g_csr[i] = rec;
    }
}

// ---------------------------------------------------------------------------
// Main: one block = G=4 batch rows. Axial staged transposed (elem-major,
// float4 over g) so each edge gather is a single LDS.128; each edge record is
// a single LDG.128. Fused squared-error reduction; last block finalizes.
// ---------------------------------------------------------------------------
__global__ __launch_bounds__(THREADS)
void nel_main_kernel(const float* __restrict__ EA,
                     const float* __restrict__ e,
                     const float* __restrict__ q,
                     const float* __restrict__ r,
                     float* __restrict__ out) {
    __shared__ float s_axial[N_ELEM * G];    // 32 KB, layout [elem][g]
    __shared__ float s_warp[THREADS / 32];
    __shared__ int   s_islast;

    const int tid = threadIdx.x;
    const int b0  = blockIdx.x * G;

    // --- stage axial = EA*e, transposed: s_axial[elem*4 + g] ---
    {
        const int g  = tid & 3;
        const int c0 = tid >> 2;             // 0..63 (float4 column)
        const float4* EA4 = (const float4*)(EA + (size_t)(b0 + g) * N_ELEM);
        const float4* e4  = (const float4*)(e  + (size_t)(b0 + g) * N_ELEM);
        #pragma unroll
        for (int k = 0; k < (N_ELEM / 4) / 64; k++) {   // 8 iters
            int col = c0 + 64 * k;
            float4 a  = EA4[col];
            float4 ee = e4[col];
            int base = col * 16 + g;
            s_axial[base + 0]  = a.x * ee.x;
            s_axial[base + 4]  = a.y * ee.y;
            s_axial[base + 8]  = a.z * ee.z;
            s_axial[base + 12] = a.w * ee.w;
        }
    }
    __syncthreads();

    // --- gather per node (vectorized over the 4 batches), fuse loss ---
    const float4* sax4 = (const float4*)s_axial;
    float acc = 0.f;

    #pragma unroll
    for (int nn = 0; nn < N_NODES / THREADS; nn++) {    // 4 iters
        const int n   = tid + nn * THREADS;
        const int beg = g_csr_off[n];
        const int end = g_csr_off[n + 1];

        float4 ax = make_float4(0.f, 0.f, 0.f, 0.f);    // x-comp, g=0..3
        float4 ay = make_float4(0.f, 0.f, 0.f, 0.f);    // y-comp, g=0..3
        for (int p = beg; p < end; p++) {
            float4 rec = g_csr[p];                      // LDG.128
            int eid = __float_as_int(rec.x);
            float4 a = sax4[eid];                       // LDS.128
            ax.x += a.x * rec.y;  ax.y += a.y * rec.y;
            ax.z += a.z * rec.y;  ax.w += a.w * rec.y;
            ay.x += a.x * rec.z;  ay.y += a.y * rec.z;
            ay.z += a.z * rec.z;  ay.w += a.w * rec.z;
        }

        const float* axp = (const float*)&ax;
        const float* ayp = (const float*)&ay;
        #pragma unroll
        for (int g = 0; g < G; g++) {
            const float2* q2 = (const float2*)(q + (size_t)(b0 + g) * N_NODES * 2);
            const float2* r2 = (const float2*)(r + (size_t)(b0 + g) * N_NODES * 2);
            float2 qq = q2[n];
            float2 rr = r2[n];
            float dx = axp[g] - qq.x - rr.x;
            float dy = ayp[g] - qq.y - rr.y;
            acc += dx * dx + dy * dy;
        }
    }

    // --- block reduce ---
    #pragma unroll
    for (int o = 16; o > 0; o >>= 1)
        acc += __shfl_down_sync(0xffffffffu, acc, o);
    if ((tid & 31) == 0) s_warp[tid >> 5] = acc;
    __syncthreads();
    if (tid == 0) {
        float total = 0.f;
        #pragma unroll
        for (int w = 0; w < THREADS / 32; w++) total += s_warp[w];
        g_part[blockIdx.x] = total;
    }

    // --- last-block finalize (fixed-order double sum -> deterministic) ---
    __threadfence();
    if (tid == 0) {
        int old = atomicAdd(&g_ctr, 1);
        s_islast = (old == (int)gridDim.x - 1) ? 1 : 0;
    }
    __syncthreads();
    if (s_islast) {
        __threadfence();
        __shared__ double s_d[THREADS];
        double d = 0.0;
        #pragma unroll
        for (int i = tid; i < NBLK; i += THREADS) d += (double)g_part[i];
        s_d[tid] = d;
        __syncthreads();
        #pragma unroll
        for (int s = THREADS / 2; s > 0; s >>= 1) {
            if (tid < s) s_d[tid] += s_d[tid + s];
            __syncthreads();
        }
        if (tid == 0) {
            out[0] = (float)(s_d[0] / ((double)B * (double)N_NODES * 2.0));
            g_ctr = 0;   // reset for next graph replay
        }
    }
}

extern "C" void kernel_launch(void* const* d_in, const int* in_sizes, int n_in,
                              void* d_out, int out_size) {
    const float* EA       = (const float*)d_in[0];
    const float* e        = (const float*)d_in[1];
    const float* q        = (const float*)d_in[2];
    const float* r        = (const float*)d_in[3];
    const float* vecs     = (const float*)d_in[4];
    const int*   node_ids = (const int*)d_in[5];
    const int*   elem_ids = (const int*)d_in[6];
    float* out = (float*)d_out;

    nel_setup_kernel<<<1, N_NODES>>>(node_ids, elem_ids, vecs);
    nel_main_kernel<<<NBLK, THREADS>>>(EA, e, q, r, out);
}